// round 3
// baseline (speedup 1.0000x reference)
#include <cuda_runtime.h>
#include <math.h>

// Problem shape (fixed for this dataset)
#define BB 8
#define NN 2048
#define MM 2048
#define DD 256

// GEMM tiling
#define BN 128
#define BM 128
#define BK 16
#define SST 132           // Bs shared stride (floats)
#define AST 264           // As2 shared stride (floats, duplicated columns: 2*128 + 8 pad)

typedef unsigned long long ull;

// Scratch: inverse norms
__device__ float g_invx[BB * NN];
__device__ float g_invy[BB * MM];

// Packed dual-fp32 FMA: d = a * b + c, lanewise on 2 packed floats.
#define FMA2(d, a, b, c) \
    asm("fma.rn.f32x2 %0, %1, %2, %3;" : "=l"(d) : "l"(a), "l"(b), "l"(c))

__device__ __forceinline__ ull pack_dup(float v) {
    ull r;
    asm("mov.b64 %0, {%1, %1};" : "=l"(r) : "f"(v));
    return r;
}
__device__ __forceinline__ float unpack_lo(ull v) {
    float lo, hi;
    asm("mov.b64 {%0, %1}, %2;" : "=f"(lo), "=f"(hi) : "l"(v));
    return lo;
}
__device__ __forceinline__ float unpack_hi(ull v) {
    float lo, hi;
    asm("mov.b64 {%0, %1}, %2;" : "=f"(lo), "=f"(hi) : "l"(v));
    return hi;
}

// ---------------------------------------------------------------------------
// Kernel 1: per-row inverse L2 norms for src and dst descriptors.
// One warp per row (256 floats = 2 float4 per lane).
// ---------------------------------------------------------------------------
__global__ void norms_kernel(const float* __restrict__ src,
                             const float* __restrict__ dst) {
    int gwarp = (blockIdx.x * blockDim.x + threadIdx.x) >> 5;
    int lane  = threadIdx.x & 31;
    const int total = BB * NN + BB * MM;
    if (gwarp >= total) return;

    const float* p;
    float* outp;
    if (gwarp < BB * NN) {
        p = src + (size_t)gwarp * DD;
        outp = &g_invx[gwarp];
    } else {
        int r = gwarp - BB * NN;
        p = dst + (size_t)r * DD;
        outp = &g_invy[r];
    }
    const float4* p4 = (const float4*)p;
    float4 v0 = p4[lane];
    float4 v1 = p4[lane + 32];
    float s = v0.x * v0.x + v0.y * v0.y + v0.z * v0.z + v0.w * v0.w
            + v1.x * v1.x + v1.y * v1.y + v1.z * v1.z + v1.w * v1.w;
#pragma unroll
    for (int o = 16; o > 0; o >>= 1)
        s += __shfl_xor_sync(0xffffffffu, s, o);
    if (lane == 0) {
        float nrm = sqrtf(s);
        *outp = 1.0f / fmaxf(nrm, 1e-12f);
    }
}

// ---------------------------------------------------------------------------
// Kernel 2: fused cosine-sim GEMM (packed f32x2 FMAs) + running argmax + gather.
// Block: 256 threads = 16x16, 8(N) x 8(M) register tile -> 128x128 block tile.
// As is stored column-DUPLICATED in smem so each LDS.128 yields two ready
// (a,a) packed operands; Bs pairs (b_j, b_j+1) are naturally packed.
// ---------------------------------------------------------------------------
__global__ __launch_bounds__(256, 2)
void match_kernel(const float* __restrict__ A,      // [B,N,D] src
                  const float* __restrict__ Bd,     // [B,M,D] dst
                  const float* __restrict__ pts,    // [B,M,2]
                  float* __restrict__ out) {        // [B*N*2 matched | B*N conf]
    __shared__ float As2[BK * AST];   // duplicated: value n at cols 2n, 2n+1
    __shared__ float Bs[BK * SST];

    const int b  = blockIdx.y;
    const int n0 = blockIdx.x * BN;
    const int tid = threadIdx.x;
    const int tx = tid & 15;
    const int ty = tid >> 4;

    const float* Ab = A  + (size_t)b * NN * DD;
    const float* Bb = Bd + (size_t)b * MM * DD;
    const float* invy_b = &g_invy[b * MM];

    float best[8];
    int   bidx[8];
#pragma unroll
    for (int i = 0; i < 8; i++) { best[i] = -1e30f; bidx[i] = 0; }

    // Tile-load index precompute: each thread moves 2 float4 per matrix.
    const int f0  = tid;
    const int an0 = f0 >> 2;          // tile row 0..63
    const int ac0 = (f0 & 3) * 4;     // k offset 0,4,8,12
    const int f1  = tid + 256;
    const int an1 = f1 >> 2;          // tile row 64..127
    const int ac1 = (f1 & 3) * 4;

    for (int mt = 0; mt < MM; mt += BM) {
        ull acc2[8][4];
#pragma unroll
        for (int i = 0; i < 8; i++)
#pragma unroll
            for (int j = 0; j < 4; j++) acc2[i][j] = 0ull;

        for (int kt = 0; kt < DD; kt += BK) {
            float4 a0v = *(const float4*)(Ab + (size_t)(n0 + an0) * DD + kt + ac0);
            float4 a1v = *(const float4*)(Ab + (size_t)(n0 + an1) * DD + kt + ac1);
            float4 b0v = *(const float4*)(Bb + (size_t)(mt + an0) * DD + kt + ac0);
            float4 b1v = *(const float4*)(Bb + (size_t)(mt + an1) * DD + kt + ac1);

            __syncthreads();   // previous iter's smem reads complete
            // A: store duplicated pairs (v,v) as 8-byte stores
            *(ull*)&As2[(ac0 + 0) * AST + 2 * an0] = pack_dup(a0v.x);
            *(ull*)&As2[(ac0 + 1) * AST + 2 * an0] = pack_dup(a0v.y);
            *(ull*)&As2[(ac0 + 2) * AST + 2 * an0] = pack_dup(a0v.z);
            *(ull*)&As2[(ac0 + 3) * AST + 2 * an0] = pack_dup(a0v.w);
            *(ull*)&As2[(ac1 + 0) * AST + 2 * an1] = pack_dup(a1v.x);
            *(ull*)&As2[(ac1 + 1) * AST + 2 * an1] = pack_dup(a1v.y);
            *(ull*)&As2[(ac1 + 2) * AST + 2 * an1] = pack_dup(a1v.z);
            *(ull*)&As2[(ac1 + 3) * AST + 2 * an1] = pack_dup(a1v.w);
            // B: plain transposed store
            Bs[(ac0 + 0) * SST + an0] = b0v.x;
            Bs[(ac0 + 1) * SST + an0] = b0v.y;
            Bs[(ac0 + 2) * SST + an0] = b0v.z;
            Bs[(ac0 + 3) * SST + an0] = b0v.w;
            Bs[(ac1 + 0) * SST + an1] = b1v.x;
            Bs[(ac1 + 1) * SST + an1] = b1v.y;
            Bs[(ac1 + 2) * SST + an1] = b1v.z;
            Bs[(ac1 + 3) * SST + an1] = b1v.w;
            __syncthreads();

#pragma unroll
            for (int k = 0; k < BK; k++) {
                // A operands: 4x LDS.128, each = two packed (a,a) duplicates
                const ulonglong2* ap = (const ulonglong2*)&As2[k * AST + 16 * ty];
                ulonglong2 A0 = ap[0], A1 = ap[1], A2 = ap[2], A3 = ap[3];
                ull a_[8] = {A0.x, A0.y, A1.x, A1.y, A2.x, A2.y, A3.x, A3.y};
                // B operands: 2x LDS.128, each = two packed (b_j, b_j+1) pairs
                const ulonglong2* bp = (const ulonglong2*)&Bs[k * SST + 8 * tx];
                ulonglong2 B0 = bp[0], B1 = bp[1];
                ull b_[4] = {B0.x, B0.y, B1.x, B1.y};
#pragma unroll
                for (int i = 0; i < 8; i++)
#pragma unroll
                    for (int j = 0; j < 4; j++)
                        FMA2(acc2[i][j], a_[i], b_[j], acc2[i][j]);
            }
        }

        // Fold this M-tile into the running per-row argmax (ascending m).
#pragma unroll
        for (int j = 0; j < 4; j++) {
            const int m = mt + 8 * tx + 2 * j;
            const float iv0 = __ldg(&invy_b[m]);
            const float iv1 = __ldg(&invy_b[m + 1]);
#pragma unroll
            for (int i = 0; i < 8; i++) {
                float t0 = unpack_lo(acc2[i][j]) * iv0;
                if (t0 > best[i]) { best[i] = t0; bidx[i] = m; }
                float t1 = unpack_hi(acc2[i][j]) * iv1;
                if (t1 > best[i]) { best[i] = t1; bidx[i] = m + 1; }
            }
        }
    }

    // Cross-lane reduce over tx (lanes 0-15 / 16-31 are independent halves;
    // xor strides < 16 never cross halves).
#pragma unroll
    for (int s = 1; s < 16; s <<= 1) {
#pragma unroll
        for (int i = 0; i < 8; i++) {
            float ov = __shfl_xor_sync(0xffffffffu, best[i], s);
            int   oi = __shfl_xor_sync(0xffffffffu, bidx[i], s);
            if (ov > best[i] || (ov == best[i] && oi < bidx[i])) {
                best[i] = ov; bidx[i] = oi;
            }
        }
    }

    if (tx == 0) {
#pragma unroll
        for (int i = 0; i < 8; i++) {
            const int n  = n0 + 8 * ty + i;
            const int gi = b * NN + n;
            out[(size_t)BB * NN * 2 + gi] = best[i] * g_invx[gi];  // confidence
            const float* pp = pts + ((size_t)b * MM + bidx[i]) * 2;
            out[(size_t)gi * 2 + 0] = pp[0];                        // matched x
            out[(size_t)gi * 2 + 1] = pp[1];                        // matched y
        }
    }
}

// ---------------------------------------------------------------------------
extern "C" void kernel_launch(void* const* d_in, const int* in_sizes, int n_in,
                              void* d_out, int out_size) {
    const float* desc_src   = (const float*)d_in[0];
    const float* desc_dst   = (const float*)d_in[1];
    const float* points_dst = (const float*)d_in[2];
    float* out = (float*)d_out;

    const int total_rows = BB * NN + BB * MM;
    norms_kernel<<<(total_rows + 7) / 8, 256>>>(desc_src, desc_dst);

    dim3 grid(NN / BN, BB);
    match_kernel<<<grid, 256>>>(desc_src, desc_dst, points_dst, out);
}

// round 5
// speedup vs baseline: 2.0779x; 2.0779x over previous
#include <cuda_runtime.h>
#include <math.h>
#include <stdint.h>

// Problem shape (fixed)
#define BB 8
#define NN 2048
#define MM 2048
#define DD 256

#define TOT (BB * NN * DD)

// tf32-split scratch (hi = round-to-nearest tf32, lo = fp32 residual)
__device__ float g_Ah[TOT];
__device__ float g_Al[TOT];
__device__ float g_Bh[TOT];
__device__ float g_Bl[TOT];
__device__ float g_invx[BB * NN];
__device__ float g_invy[BB * MM];

// ---------------------------------------------------------------------------
// PTX helpers (all baseline sm_80-class: work on plain sm_103 target)
// ---------------------------------------------------------------------------
__device__ __forceinline__ uint32_t smem_u32(const void* p) {
    uint32_t a;
    asm("{ .reg .u64 t; cvta.to.shared.u64 t, %1; cvt.u32.u64 %0, t; }"
        : "=r"(a) : "l"(p));
    return a;
}
__device__ __forceinline__ float tf32_rna(float x) {
    float r;
    asm("cvt.rna.tf32.f32 %0, %1;" : "=f"(r) : "f"(x));
    return r;
}
#define CP16(sm, gp) \
    asm volatile("cp.async.cg.shared.global [%0], [%1], 16;" \
                 :: "r"(sm), "l"(gp) : "memory")
#define CP_WAIT_ALL() asm volatile("cp.async.wait_all;" ::: "memory")

__device__ __forceinline__ void ldm4(uint32_t* r, uint32_t addr) {
    asm volatile("ldmatrix.sync.aligned.m8n8.x4.shared.b16 {%0,%1,%2,%3}, [%4];"
        : "=r"(r[0]), "=r"(r[1]), "=r"(r[2]), "=r"(r[3]) : "r"(addr));
}
__device__ __forceinline__ void ldm2(uint32_t* r, uint32_t addr) {
    asm volatile("ldmatrix.sync.aligned.m8n8.x2.shared.b16 {%0,%1}, [%2];"
        : "=r"(r[0]), "=r"(r[1]) : "r"(addr));
}
__device__ __forceinline__ void mma_tf32(float* d, const uint32_t* a, const uint32_t* b) {
    asm volatile("mma.sync.aligned.m16n8k8.row.col.f32.tf32.tf32.f32 "
        "{%0,%1,%2,%3}, {%4,%5,%6,%7}, {%8,%9}, {%0,%1,%2,%3};"
        : "+f"(d[0]), "+f"(d[1]), "+f"(d[2]), "+f"(d[3])
        : "r"(a[0]), "r"(a[1]), "r"(a[2]), "r"(a[3]), "r"(b[0]), "r"(b[1]));
}

// ---------------------------------------------------------------------------
// Kernel 1: fused per-row norm + tf32 split. One warp per row (256 floats).
// ---------------------------------------------------------------------------
__global__ void prep_kernel(const float* __restrict__ src,
                            const float* __restrict__ dst) {
    int gwarp = (blockIdx.x * blockDim.x + threadIdx.x) >> 5;
    int lane  = threadIdx.x & 31;
    const int total = BB * NN + BB * MM;
    if (gwarp >= total) return;

    const float* p;
    float *outp, *ho, *lo;
    size_t ro;
    if (gwarp < BB * NN) {
        ro = (size_t)gwarp * DD;
        p = src + ro; ho = g_Ah + ro; lo = g_Al + ro; outp = &g_invx[gwarp];
    } else {
        int r = gwarp - BB * NN;
        ro = (size_t)r * DD;
        p = dst + ro; ho = g_Bh + ro; lo = g_Bl + ro; outp = &g_invy[r];
    }
    float s = 0.0f;
#pragma unroll
    for (int h = 0; h < 2; h++) {
        float4 v = ((const float4*)p)[lane + 32 * h];
        s += v.x * v.x + v.y * v.y + v.z * v.z + v.w * v.w;
        float4 hi, lw;
        hi.x = tf32_rna(v.x); lw.x = v.x - hi.x;
        hi.y = tf32_rna(v.y); lw.y = v.y - hi.y;
        hi.z = tf32_rna(v.z); lw.z = v.z - hi.z;
        hi.w = tf32_rna(v.w); lw.w = v.w - hi.w;
        ((float4*)ho)[lane + 32 * h] = hi;
        ((float4*)lo)[lane + 32 * h] = lw;
    }
#pragma unroll
    for (int o = 16; o > 0; o >>= 1) s += __shfl_xor_sync(0xffffffffu, s, o);
    if (lane == 0) *outp = 1.0f / fmaxf(sqrtf(s), 1e-12f);
}

// ---------------------------------------------------------------------------
// Kernel 2: HMMA tf32 (3-term split) GEMM + running argmax + gather.
// CTA = 128 src rows x 1 batch, 256 threads (8 warps = 2(n) x 4(m)).
// Warp tile 64(n) x 32(m). K streamed in 8 chunks of 32 floats.
// smem buffer layout per stage: Ah | Al | Bh | Bl, each 128 rows x 128B, swizzled.
// ---------------------------------------------------------------------------
#define AH_OFF 0
#define AL_OFF 16384
#define BH_OFF 32768
#define BL_OFF 49152
#define BUF_B  65536
#define SM_HDR 1024                    // invy_s[2][128] floats
#define SMEM_SZ (SM_HDR + 2 * BUF_B)   // 132096

__global__ __launch_bounds__(256, 1)
void match_kernel(const float* __restrict__ pts,   // [B,M,2]
                  float* __restrict__ out) {       // [B*N*2 matched | B*N conf]
    extern __shared__ char smem[];
    const uint32_t sb = smem_u32(smem);
    const int tid  = threadIdx.x;
    const int wid  = tid >> 5;
    const int lane = tid & 31;
    const int b    = blockIdx.y;
    const int n0   = blockIdx.x * 128;
    const int warpN = wid >> 2;        // 0..1 -> n offset 64*warpN
    const int warpM = wid & 3;         // 0..3 -> m offset 32*warpM

    const float* Ahp = g_Ah + ((size_t)b * NN + n0) * DD;
    const float* Alp = g_Al + ((size_t)b * NN + n0) * DD;
    const float* Bhp = g_Bh + (size_t)b * MM * DD;
    const float* Blp = g_Bl + (size_t)b * MM * DD;
    const float* invy_b = &g_invy[b * MM];

    // --- staging geometry: 4 x float4 per 16KB tile per thread ---
    int row_[4], swo_[4], go_[4];
#pragma unroll
    for (int r = 0; r < 4; r++) {
        int id = tid + 256 * r;
        int row = id >> 3;             // 0..127
        int c4  = id & 7;              // 16B column
        row_[r] = row;
        swo_[r] = row * 128 + ((c4 ^ (row & 7)) << 4);
        go_[r]  = row * DD + c4 * 4;
    }

    // --- ldmatrix fragment addresses (offsets within a 16KB tile) ---
    const int q  = lane >> 3;          // x4 matrix id
    const int q0 = q & 1;              // row block (+8)
    const int q1 = q >> 1;             // col block (+16B)
    const int r8 = lane & 7;
    int aBase[4], bBase[4], aXor[4], bXor[4];
#pragma unroll
    for (int i = 0; i < 4; i++)
        aBase[i] = (warpN * 64 + i * 16 + q0 * 8 + r8) * 128;
#pragma unroll
    for (int j = 0; j < 4; j++)
        bBase[j] = (warpM * 32 + j * 8 + r8) * 128;
    const int hB = (lane >> 3) & 1;    // x2 matrix id
#pragma unroll
    for (int s = 0; s < 4; s++) {
        aXor[s] = (((s * 2 + q1) ^ r8) << 4);
        bXor[s] = (((s * 2 + hB) ^ r8) << 4);
    }

    float best[8];
    int   bidx[8];
#pragma unroll
    for (int k = 0; k < 8; k++) { best[k] = -1e30f; bidx[k] = 0; }

    // --- prologue: stage chunk (mt=0, kc=0) into buf0, invy tile 0 ---
#pragma unroll
    for (int r = 0; r < 4; r++) {
        uint32_t db = sb + SM_HDR;
        CP16(db + AH_OFF + swo_[r], Ahp + go_[r]);
        CP16(db + AL_OFF + swo_[r], Alp + go_[r]);
        CP16(db + BH_OFF + swo_[r], Bhp + go_[r]);
        CP16(db + BL_OFF + swo_[r], Blp + go_[r]);
    }
    if (tid < 32) CP16(sb + (tid << 4), invy_b + tid * 4);
    CP_WAIT_ALL();
    __syncthreads();

    int it = 0;
    for (int mtIdx = 0; mtIdx < 16; mtIdx++) {
        const int mt = mtIdx * 128;
        float acc[4][4][4];
#pragma unroll
        for (int i = 0; i < 4; i++)
#pragma unroll
            for (int j = 0; j < 4; j++)
#pragma unroll
                for (int d = 0; d < 4; d++) acc[i][j][d] = 0.0f;

        for (int c = 0; c < 8; c++, it++) {
            const int p = it & 1;
            // stage next chunk (possibly next mt's chunk 0)
            if (it < 127) {
                const int nit = it + 1;
                const int nmt = (nit >> 3) * 128;
                const int nkc = (nit & 7) * 32;
                const uint32_t db = sb + SM_HDR + (nit & 1) * BUF_B;
                const size_t bo = (size_t)nmt * DD + nkc;
#pragma unroll
                for (int r = 0; r < 4; r++) {
                    CP16(db + AH_OFF + swo_[r], Ahp + go_[r] + nkc);
                    CP16(db + AL_OFF + swo_[r], Alp + go_[r] + nkc);
                    CP16(db + BH_OFF + swo_[r], Bhp + bo + go_[r]);
                    CP16(db + BL_OFF + swo_[r], Blp + bo + go_[r]);
                }
                if ((nit & 7) == 0 && tid < 32)
                    CP16(sb + (((nit >> 3) & 1) << 9) + (tid << 4),
                         invy_b + nmt + tid * 4);
            }
            // compute on buf p
            const uint32_t bb = sb + SM_HDR + p * BUF_B;
#pragma unroll
            for (int s = 0; s < 4; s++) {
                uint32_t ah[4][4], al[4][4], bh[4][2], bl[4][2];
#pragma unroll
                for (int i = 0; i < 4; i++) {
                    ldm4(ah[i], bb + AH_OFF + aBase[i] + aXor[s]);
                    ldm4(al[i], bb + AL_OFF + aBase[i] + aXor[s]);
                }
#pragma unroll
                for (int j = 0; j < 4; j++) {
                    ldm2(bh[j], bb + BH_OFF + bBase[j] + bXor[s]);
                    ldm2(bl[j], bb + BL_OFF + bBase[j] + bXor[s]);
                }
#pragma unroll
                for (int i = 0; i < 4; i++)
#pragma unroll
                    for (int j = 0; j < 4; j++) {
                        mma_tf32(acc[i][j], ah[i], bh[j]);   // hi*hi
                        mma_tf32(acc[i][j], ah[i], bl[j]);   // hi*lo
                        mma_tf32(acc[i][j], al[i], bh[j]);   // lo*hi
                    }
            }
            CP_WAIT_ALL();
            __syncthreads();
        }

        // --- epilogue: fold this M-tile into running per-row argmax ---
        const float* iv = (const float*)(smem + ((mtIdx & 1) << 9));
#pragma unroll
        for (int i = 0; i < 4; i++) {
            const int k0 = i * 2, k1 = i * 2 + 1;
#pragma unroll
            for (int j = 0; j < 4; j++) {
                const int mc = warpM * 32 + j * 8 + 2 * (lane & 3);
                const int gm = mt + mc;
                const float iv0 = iv[mc], iv1 = iv[mc + 1];
                float v0 = acc[i][j][0] * iv0;
                float v1 = acc[i][j][1] * iv1;
                float v2 = acc[i][j][2] * iv0;
                float v3 = acc[i][j][3] * iv1;
                if (v0 > best[k0]) { best[k0] = v0; bidx[k0] = gm; }
                if (v1 > best[k0]) { best[k0] = v1; bidx[k0] = gm + 1; }
                if (v2 > best[k1]) { best[k1] = v2; bidx[k1] = gm; }
                if (v3 > best[k1]) { best[k1] = v3; bidx[k1] = gm + 1; }
            }
        }
    }

    // --- reduce across the 4 lanes sharing each row (lane&3 varies) ---
#pragma unroll
    for (int s = 1; s < 4; s <<= 1) {
#pragma unroll
        for (int k = 0; k < 8; k++) {
            float ov = __shfl_xor_sync(0xffffffffu, best[k], s);
            int   oi = __shfl_xor_sync(0xffffffffu, bidx[k], s);
            if (ov > best[k] || (ov == best[k] && oi < bidx[k])) {
                best[k] = ov; bidx[k] = oi;
            }
        }
    }

    // --- cross-warpM reduce via smem (alias the dead stage buffers) ---
    float (*sb_best)[128] = (float(*)[128])(smem + SM_HDR);
    int   (*sb_idx)[128]  = (int(*)[128])(smem + SM_HDR + 2048);
    if ((lane & 3) == 0) {
#pragma unroll
        for (int k = 0; k < 8; k++) {
            int row = warpN * 64 + (k >> 1) * 16 + (k & 1) * 8 + (lane >> 2);
            sb_best[warpM][row] = best[k];
            sb_idx[warpM][row]  = bidx[k];
        }
    }
    __syncthreads();

    if (tid < 128) {
        float fb = sb_best[0][tid];
        int   fi = sb_idx[0][tid];
#pragma unroll
        for (int w = 1; w < 4; w++) {
            float ov = sb_best[w][tid];
            int   oi = sb_idx[w][tid];
            if (ov > fb || (ov == fb && oi < fi)) { fb = ov; fi = oi; }
        }
        const int n  = n0 + tid;
        const int gi = b * NN + n;
        out[(size_t)BB * NN * 2 + gi] = fb * g_invx[gi];   // confidence
        const float* pp = pts + ((size_t)b * MM + fi) * 2;
        out[(size_t)gi * 2 + 0] = pp[0];                    // matched x
        out[(size_t)gi * 2 + 1] = pp[1];                    // matched y
    }
}

// ---------------------------------------------------------------------------
extern "C" void kernel_launch(void* const* d_in, const int* in_sizes, int n_in,
                              void* d_out, int out_size) {
    const float* desc_src   = (const float*)d_in[0];
    const float* desc_dst   = (const float*)d_in[1];
    const float* points_dst = (const float*)d_in[2];
    float* out = (float*)d_out;

    static int configured = 0;
    cudaFuncSetAttribute(match_kernel,
                         cudaFuncAttributeMaxDynamicSharedMemorySize, SMEM_SZ);
    (void)configured;

    const int total_rows = BB * NN + BB * MM;   // 32768 rows, 1 warp each
    prep_kernel<<<(total_rows + 7) / 8, 256>>>(desc_src, desc_dst);

    dim3 grid(NN / 128, BB);
    match_kernel<<<grid, 256, SMEM_SZ>>>(points_dst, out);
}

// round 6
// speedup vs baseline: 2.0916x; 1.0066x over previous
#include <cuda_runtime.h>
#include <math.h>
#include <stdint.h>

// Problem shape (fixed)
#define BB 8
#define NN 2048
#define MM 2048
#define DD 256

#define TOT (BB * NN * DD)

// tf32-split scratch (hi = round-to-nearest tf32, lo = fp32 residual)
__device__ float g_Ah[TOT];
__device__ float g_Al[TOT];
__device__ float g_Bh[TOT];
__device__ float g_Bl[TOT];
__device__ float g_invx[BB * NN];
__device__ float g_invy[BB * MM];

// ---------------------------------------------------------------------------
// PTX helpers (baseline sm_80-class; valid on plain sm_103 target)
// ---------------------------------------------------------------------------
__device__ __forceinline__ uint32_t smem_u32(const void* p) {
    uint32_t a;
    asm("{ .reg .u64 t; cvta.to.shared.u64 t, %1; cvt.u32.u64 %0, t; }"
        : "=r"(a) : "l"(p));
    return a;
}
__device__ __forceinline__ float tf32_rna(float x) {
    float r;
    asm("cvt.rna.tf32.f32 %0, %1;" : "=f"(r) : "f"(x));
    return r;
}
#define CP16(sm, gp) \
    asm volatile("cp.async.cg.shared.global [%0], [%1], 16;" \
                 :: "r"(sm), "l"(gp) : "memory")
#define CP_WAIT_ALL() asm volatile("cp.async.wait_all;" ::: "memory")

__device__ __forceinline__ void ldm4(uint32_t* r, uint32_t addr) {
    asm volatile("ldmatrix.sync.aligned.m8n8.x4.shared.b16 {%0,%1,%2,%3}, [%4];"
        : "=r"(r[0]), "=r"(r[1]), "=r"(r[2]), "=r"(r[3]) : "r"(addr));
}
__device__ __forceinline__ void mma_tf32(float* d, const uint32_t* a, const uint32_t* b) {
    asm volatile("mma.sync.aligned.m16n8k8.row.col.f32.tf32.tf32.f32 "
        "{%0,%1,%2,%3}, {%4,%5,%6,%7}, {%8,%9}, {%0,%1,%2,%3};"
        : "+f"(d[0]), "+f"(d[1]), "+f"(d[2]), "+f"(d[3])
        : "r"(a[0]), "r"(a[1]), "r"(a[2]), "r"(a[3]), "r"(b[0]), "r"(b[1]));
}

// ---------------------------------------------------------------------------
// Kernel 1: fused per-row norm + tf32 split. One warp per row (256 floats).
// ---------------------------------------------------------------------------
__global__ void prep_kernel(const float* __restrict__ src,
                            const float* __restrict__ dst) {
    int gwarp = (blockIdx.x * blockDim.x + threadIdx.x) >> 5;
    int lane  = threadIdx.x & 31;
    const int total = BB * NN + BB * MM;
    if (gwarp >= total) return;

    const float* p;
    float *outp, *ho, *lo;
    size_t ro;
    if (gwarp < BB * NN) {
        ro = (size_t)gwarp * DD;
        p = src + ro; ho = g_Ah + ro; lo = g_Al + ro; outp = &g_invx[gwarp];
    } else {
        int r = gwarp - BB * NN;
        ro = (size_t)r * DD;
        p = dst + ro; ho = g_Bh + ro; lo = g_Bl + ro; outp = &g_invy[r];
    }
    float s = 0.0f;
#pragma unroll
    for (int h = 0; h < 2; h++) {
        float4 v = ((const float4*)p)[lane + 32 * h];
        s += v.x * v.x + v.y * v.y + v.z * v.z + v.w * v.w;
        float4 hi, lw;
        hi.x = tf32_rna(v.x); lw.x = v.x - hi.x;
        hi.y = tf32_rna(v.y); lw.y = v.y - hi.y;
        hi.z = tf32_rna(v.z); lw.z = v.z - hi.z;
        hi.w = tf32_rna(v.w); lw.w = v.w - hi.w;
        ((float4*)ho)[lane + 32 * h] = hi;
        ((float4*)lo)[lane + 32 * h] = lw;
    }
#pragma unroll
    for (int o = 16; o > 0; o >>= 1) s += __shfl_xor_sync(0xffffffffu, s, o);
    if (lane == 0) *outp = 1.0f / fmaxf(sqrtf(s), 1e-12f);
}

// ---------------------------------------------------------------------------
// Kernel 2: HMMA tf32 (3-term split) GEMM + running argmax + gather.
// CTA = 64 src rows x 1 batch, 256 threads (8 warps = 2(n) x 4(m)),
// 2 CTAs co-resident per SM. Warp tile 32(n) x 32(m).
// K streamed in 8 chunks of 32 floats; double-buffered cp.async.
// ---------------------------------------------------------------------------
#define AH_OFF 0
#define AL_OFF 8192
#define BH_OFF 16384
#define BL_OFF 32768
#define STAGE_B 49152
#define SM_HDR 1024                     // invy double buffer 2x512B
#define SMEM_SZ (SM_HDR + 2 * STAGE_B)  // 99328

__global__ __launch_bounds__(256, 2)
void match_kernel(const float* __restrict__ pts,   // [B,M,2]
                  float* __restrict__ out) {       // [B*N*2 matched | B*N conf]
    extern __shared__ char smem[];
    const uint32_t sb = smem_u32(smem);
    const int tid  = threadIdx.x;
    const int wid  = tid >> 5;
    const int lane = tid & 31;
    const int b    = blockIdx.y;
    const int n0   = blockIdx.x * 64;
    const int warpN = wid >> 2;        // 0..1 -> n offset 32*warpN
    const int warpM = wid & 3;         // 0..3 -> m offset 32*warpM

    const float* Ahp = g_Ah + ((size_t)b * NN + n0) * DD;
    const float* Alp = g_Al + ((size_t)b * NN + n0) * DD;
    const float* Bhp = g_Bh + (size_t)b * MM * DD;
    const float* Blp = g_Bl + (size_t)b * MM * DD;
    const float* invy_b = &g_invy[b * MM];

    // --- staging geometry ---
    // A tiles: 64 rows x 128B = 512 float4 -> 2 per thread
    int aswo[2], ago[2];
#pragma unroll
    for (int r = 0; r < 2; r++) {
        int id = tid + 256 * r;
        int row = id >> 3, c4 = id & 7;
        aswo[r] = row * 128 + ((c4 ^ (row & 7)) << 4);
        ago[r]  = row * DD + c4 * 4;
    }
    // B tiles: 128 rows x 128B = 1024 float4 -> 4 per thread
    int bswo[4], bgo[4];
#pragma unroll
    for (int r = 0; r < 4; r++) {
        int id = tid + 256 * r;
        int row = id >> 3, c4 = id & 7;
        bswo[r] = row * 128 + ((c4 ^ (row & 7)) << 4);
        bgo[r]  = row * DD + c4 * 4;
    }

    // --- ldmatrix fragment addresses ---
    const int q  = lane >> 3;
    const int r8 = lane & 7;
    // A: x4 load = 16x8 tf32 tile. q0=q&1 -> +8 rows, q1=q>>1 -> +16B col.
    const int q0 = q & 1, q1 = q >> 1;
    int aBase[2], aXor[4];
#pragma unroll
    for (int i = 0; i < 2; i++)
        aBase[i] = (warpN * 32 + i * 16 + q0 * 8 + r8) * 128;
    // B: x4 load = paired j-tiles (j=2t, 2t+1). qn=q>>1 -> +8 n-rows, qc=q&1 -> +16B col.
    const int qn = q >> 1, qc = q & 1;
    int bBase[2], bXor[4];
#pragma unroll
    for (int t = 0; t < 2; t++)
        bBase[t] = (warpM * 32 + t * 16 + qn * 8 + r8) * 128;
#pragma unroll
    for (int s = 0; s < 4; s++) {
        aXor[s] = (((s * 2 + q1) ^ r8) << 4);
        bXor[s] = (((s * 2 + qc) ^ r8) << 4);
    }

    float best[4];
    int   bidx[4];
#pragma unroll
    for (int k = 0; k < 4; k++) { best[k] = -1e30f; bidx[k] = 0; }

    // --- prologue: stage chunk (mt=0, kc=0) into buf0, invy tile 0 ---
    {
        const uint32_t db = sb + SM_HDR;
#pragma unroll
        for (int r = 0; r < 2; r++) {
            CP16(db + AH_OFF + aswo[r], Ahp + ago[r]);
            CP16(db + AL_OFF + aswo[r], Alp + ago[r]);
        }
#pragma unroll
        for (int r = 0; r < 4; r++) {
            CP16(db + BH_OFF + bswo[r], Bhp + bgo[r]);
            CP16(db + BL_OFF + bswo[r], Blp + bgo[r]);
        }
        if (tid < 32) CP16(sb + (tid << 4), invy_b + tid * 4);
    }
    CP_WAIT_ALL();
    __syncthreads();

    int it = 0;
    for (int mtIdx = 0; mtIdx < 16; mtIdx++) {
        const int mt = mtIdx * 128;
        float acc[2][4][4];
#pragma unroll
        for (int i = 0; i < 2; i++)
#pragma unroll
            for (int j = 0; j < 4; j++)
#pragma unroll
                for (int d = 0; d < 4; d++) acc[i][j][d] = 0.0f;

        for (int c = 0; c < 8; c++, it++) {
            const int p = it & 1;
            // stage next chunk (possibly next mt's chunk 0)
            if (it < 127) {
                const int nit = it + 1;
                const int nmt = (nit >> 3) * 128;
                const int nkc = (nit & 7) * 32;
                const uint32_t db = sb + SM_HDR + (nit & 1) * STAGE_B;
                const size_t bo = (size_t)nmt * DD + nkc;
#pragma unroll
                for (int r = 0; r < 2; r++) {
                    CP16(db + AH_OFF + aswo[r], Ahp + ago[r] + nkc);
                    CP16(db + AL_OFF + aswo[r], Alp + ago[r] + nkc);
                }
#pragma unroll
                for (int r = 0; r < 4; r++) {
                    CP16(db + BH_OFF + bswo[r], Bhp + bo + bgo[r]);
                    CP16(db + BL_OFF + bswo[r], Blp + bo + bgo[r]);
                }
                if ((nit & 7) == 0 && tid < 32)
                    CP16(sb + (((nit >> 3) & 1) << 9) + (tid << 4),
                         invy_b + nmt + tid * 4);
            }
            // compute on buf p
            const uint32_t bb = sb + SM_HDR + p * STAGE_B;
#pragma unroll
            for (int s = 0; s < 4; s++) {
                uint32_t ah[2][4], al[2][4], bh[2][4], bl[2][4];
#pragma unroll
                for (int i = 0; i < 2; i++) {
                    ldm4(ah[i], bb + AH_OFF + aBase[i] + aXor[s]);
                    ldm4(al[i], bb + AL_OFF + aBase[i] + aXor[s]);
                }
#pragma unroll
                for (int t = 0; t < 2; t++) {
                    ldm4(bh[t], bb + BH_OFF + bBase[t] + bXor[s]);
                    ldm4(bl[t], bb + BL_OFF + bBase[t] + bXor[s]);
                }
#pragma unroll
                for (int i = 0; i < 2; i++)
#pragma unroll
                    for (int j = 0; j < 4; j++) {
                        const uint32_t* bhf = &bh[j >> 1][(j & 1) * 2];
                        const uint32_t* blf = &bl[j >> 1][(j & 1) * 2];
                        mma_tf32(acc[i][j], ah[i], bhf);   // hi*hi
                        mma_tf32(acc[i][j], ah[i], blf);   // hi*lo
                        mma_tf32(acc[i][j], al[i], bhf);   // lo*hi
                    }
            }
            CP_WAIT_ALL();
            __syncthreads();
        }

        // --- epilogue: fold this M-tile into running per-row argmax ---
        const float* iv = (const float*)(smem + ((mtIdx & 1) << 9));
#pragma unroll
        for (int i = 0; i < 2; i++) {
            const int k0 = i * 2, k1 = i * 2 + 1;
#pragma unroll
            for (int j = 0; j < 4; j++) {
                const int mc = warpM * 32 + j * 8 + 2 * (lane & 3);
                const int gm = mt + mc;
                const float iv0 = iv[mc], iv1 = iv[mc + 1];
                float v0 = acc[i][j][0] * iv0;
                float v1 = acc[i][j][1] * iv1;
                float v2 = acc[i][j][2] * iv0;
                float v3 = acc[i][j][3] * iv1;
                if (v0 > best[k0]) { best[k0] = v0; bidx[k0] = gm; }
                if (v1 > best[k0]) { best[k0] = v1; bidx[k0] = gm + 1; }
                if (v2 > best[k1]) { best[k1] = v2; bidx[k1] = gm; }
                if (v3 > best[k1]) { best[k1] = v3; bidx[k1] = gm + 1; }
            }
        }
    }

    // --- reduce across the 4 lanes sharing each row (lane&3 varies) ---
#pragma unroll
    for (int s = 1; s < 4; s <<= 1) {
#pragma unroll
        for (int k = 0; k < 4; k++) {
            float ov = __shfl_xor_sync(0xffffffffu, best[k], s);
            int   oi = __shfl_xor_sync(0xffffffffu, bidx[k], s);
            if (ov > best[k] || (ov == best[k] && oi < bidx[k])) {
                best[k] = ov; bidx[k] = oi;
            }
        }
    }

    // --- cross-warpM reduce via smem (alias dead stage-0 buffer) ---
    float (*sb_best)[64] = (float(*)[64])(smem + SM_HDR);
    int   (*sb_idx)[64]  = (int(*)[64])(smem + SM_HDR + 1024);
    if ((lane & 3) == 0) {
#pragma unroll
        for (int k = 0; k < 4; k++) {
            int row = warpN * 32 + (k >> 1) * 16 + (k & 1) * 8 + (lane >> 2);
            sb_best[warpM][row] = best[k];
            sb_idx[warpM][row]  = bidx[k];
        }
    }
    __syncthreads();

    if (tid < 64) {
        float fb = sb_best[0][tid];
        int   fi = sb_idx[0][tid];
#pragma unroll
        for (int w = 1; w < 4; w++) {
            float ov = sb_best[w][tid];
            int   oi = sb_idx[w][tid];
            if (ov > fb || (ov == fb && oi < fi)) { fb = ov; fi = oi; }
        }
        const int n  = n0 + tid;
        const int gi = b * NN + n;
        out[(size_t)BB * NN * 2 + gi] = fb * g_invx[gi];   // confidence
        const float* pp = pts + ((size_t)b * MM + fi) * 2;
        out[(size_t)gi * 2 + 0] = pp[0];                    // matched x
        out[(size_t)gi * 2 + 1] = pp[1];                    // matched y
    }
}

// ---------------------------------------------------------------------------
extern "C" void kernel_launch(void* const* d_in, const int* in_sizes, int n_in,
                              void* d_out, int out_size) {
    const float* desc_src   = (const float*)d_in[0];
    const float* desc_dst   = (const float*)d_in[1];
    const float* points_dst = (const float*)d_in[2];
    float* out = (float*)d_out;

    cudaFuncSetAttribute(match_kernel,
                         cudaFuncAttributeMaxDynamicSharedMemorySize, SMEM_SZ);

    const int total_rows = BB * NN + BB * MM;   // 32768 rows, 1 warp each
    prep_kernel<<<(total_rows + 7) / 8, 256>>>(desc_src, desc_dst);

    dim3 grid(NN / 64, BB);
    match_kernel<<<grid, 256, SMEM_SZ>>>(points_dst, out);
}

// round 7
// speedup vs baseline: 2.4692x; 1.1805x over previous
#include <cuda_runtime.h>
#include <math.h>
#include <stdint.h>

// Problem shape (fixed)
#define BB 8
#define NN 2048
#define MM 2048
#define DD 256

#define TOT (BB * NN * DD)
#define NMT 16                       // number of M tiles (partials per row)

// tf32-split scratch (hi = round-to-nearest tf32, lo = fp32 residual)
__device__ float g_Ah[TOT];
__device__ float g_Al[TOT];
__device__ float g_Bh[TOT];
__device__ float g_Bl[TOT];
__device__ float g_invx[BB * NN];
__device__ float g_invy[BB * MM];
// per-(row, mtile) partial argmax
__device__ float g_pmax[BB * NN * NMT];
__device__ int   g_pidx[BB * NN * NMT];

// ---------------------------------------------------------------------------
// PTX helpers (baseline sm_80-class; valid on plain sm_103 target)
// ---------------------------------------------------------------------------
__device__ __forceinline__ uint32_t smem_u32(const void* p) {
    uint32_t a;
    asm("{ .reg .u64 t; cvta.to.shared.u64 t, %1; cvt.u32.u64 %0, t; }"
        : "=r"(a) : "l"(p));
    return a;
}
__device__ __forceinline__ float tf32_rna(float x) {
    float r;
    asm("cvt.rna.tf32.f32 %0, %1;" : "=f"(r) : "f"(x));
    return r;
}
#define CP16(sm, gp) \
    asm volatile("cp.async.cg.shared.global [%0], [%1], 16;" \
                 :: "r"(sm), "l"(gp) : "memory")
#define CP_WAIT_ALL() asm volatile("cp.async.wait_all;" ::: "memory")

__device__ __forceinline__ void ldm4(uint32_t* r, uint32_t addr) {
    asm volatile("ldmatrix.sync.aligned.m8n8.x4.shared.b16 {%0,%1,%2,%3}, [%4];"
        : "=r"(r[0]), "=r"(r[1]), "=r"(r[2]), "=r"(r[3]) : "r"(addr));
}
__device__ __forceinline__ void mma_tf32(float* d, const uint32_t* a, const uint32_t* b) {
    asm volatile("mma.sync.aligned.m16n8k8.row.col.f32.tf32.tf32.f32 "
        "{%0,%1,%2,%3}, {%4,%5,%6,%7}, {%8,%9}, {%0,%1,%2,%3};"
        : "+f"(d[0]), "+f"(d[1]), "+f"(d[2]), "+f"(d[3])
        : "r"(a[0]), "r"(a[1]), "r"(a[2]), "r"(a[3]), "r"(b[0]), "r"(b[1]));
}

// ---------------------------------------------------------------------------
// Kernel 1: fused per-row norm + tf32 split. One warp per row (256 floats).
// ---------------------------------------------------------------------------
__global__ void prep_kernel(const float* __restrict__ src,
                            const float* __restrict__ dst) {
    int gwarp = (blockIdx.x * blockDim.x + threadIdx.x) >> 5;
    int lane  = threadIdx.x & 31;
    const int total = BB * NN + BB * MM;
    if (gwarp >= total) return;

    const float* p;
    float *outp, *ho, *lo;
    size_t ro;
    if (gwarp < BB * NN) {
        ro = (size_t)gwarp * DD;
        p = src + ro; ho = g_Ah + ro; lo = g_Al + ro; outp = &g_invx[gwarp];
    } else {
        int r = gwarp - BB * NN;
        ro = (size_t)r * DD;
        p = dst + ro; ho = g_Bh + ro; lo = g_Bl + ro; outp = &g_invy[r];
    }
    float s = 0.0f;
#pragma unroll
    for (int h = 0; h < 2; h++) {
        float4 v = ((const float4*)p)[lane + 32 * h];
        s += v.x * v.x + v.y * v.y + v.z * v.z + v.w * v.w;
        float4 hi, lw;
        hi.x = tf32_rna(v.x); lw.x = v.x - hi.x;
        hi.y = tf32_rna(v.y); lw.y = v.y - hi.y;
        hi.z = tf32_rna(v.z); lw.z = v.z - hi.z;
        hi.w = tf32_rna(v.w); lw.w = v.w - hi.w;
        ((float4*)ho)[lane + 32 * h] = hi;
        ((float4*)lo)[lane + 32 * h] = lw;
    }
#pragma unroll
    for (int o = 16; o > 0; o >>= 1) s += __shfl_xor_sync(0xffffffffu, s, o);
    if (lane == 0) *outp = 1.0f / fmaxf(sqrtf(s), 1e-12f);
}

// ---------------------------------------------------------------------------
// Kernel 2: HMMA tf32 (3-term split) tile GEMM + per-tile argmax partial.
// One CTA = one 64(n) x 128(m) x 256(K) tile; grid 16(mt) x 32(nt) x 8(b).
// 256 threads (8 warps = 2(n) x 4(m)); warp tile 32x32; 2 CTAs/SM.
// K streamed in 8 chunks of 32 floats; double-buffered cp.async.
// ---------------------------------------------------------------------------
#define AH_OFF 0
#define AL_OFF 8192
#define BH_OFF 16384
#define BL_OFF 32768
#define STAGE_B 49152
#define SM_HDR 1024                     // invy tile (512B used)
#define SMEM_SZ (SM_HDR + 2 * STAGE_B)  // 99328

__global__ __launch_bounds__(256, 2)
void match_kernel() {
    extern __shared__ char smem[];
    const uint32_t sb = smem_u32(smem);
    const int tid  = threadIdx.x;
    const int wid  = tid >> 5;
    const int lane = tid & 31;
    const int mtIdx = blockIdx.x;
    const int mt   = mtIdx * 128;
    const int n0   = blockIdx.y * 64;
    const int b    = blockIdx.z;
    const int warpN = wid >> 2;        // 0..1 -> n offset 32*warpN
    const int warpM = wid & 3;         // 0..3 -> m offset 32*warpM

    const float* Ahp = g_Ah + ((size_t)b * NN + n0) * DD;
    const float* Alp = g_Al + ((size_t)b * NN + n0) * DD;
    const float* Bhp = g_Bh + ((size_t)b * MM + mt) * DD;
    const float* Blp = g_Bl + ((size_t)b * MM + mt) * DD;
    const float* invy_b = &g_invy[b * MM + mt];

    // --- staging geometry ---
    // A tiles: 64 rows x 128B = 512 float4 -> 2 per thread
    int aswo[2], ago[2];
#pragma unroll
    for (int r = 0; r < 2; r++) {
        int id = tid + 256 * r;
        int row = id >> 3, c4 = id & 7;
        aswo[r] = row * 128 + ((c4 ^ (row & 7)) << 4);
        ago[r]  = row * DD + c4 * 4;
    }
    // B tiles: 128 rows x 128B = 1024 float4 -> 4 per thread
    int bswo[4], bgo[4];
#pragma unroll
    for (int r = 0; r < 4; r++) {
        int id = tid + 256 * r;
        int row = id >> 3, c4 = id & 7;
        bswo[r] = row * 128 + ((c4 ^ (row & 7)) << 4);
        bgo[r]  = row * DD + c4 * 4;
    }

    // --- ldmatrix fragment addresses ---
    const int q  = lane >> 3;
    const int r8 = lane & 7;
    const int q0 = q & 1, q1 = q >> 1;
    int aBase[2], aXor[4];
#pragma unroll
    for (int i = 0; i < 2; i++)
        aBase[i] = (warpN * 32 + i * 16 + q0 * 8 + r8) * 128;
    const int qn = q >> 1, qc = q & 1;
    int bBase[2], bXor[4];
#pragma unroll
    for (int t = 0; t < 2; t++)
        bBase[t] = (warpM * 32 + t * 16 + qn * 8 + r8) * 128;
#pragma unroll
    for (int s = 0; s < 4; s++) {
        aXor[s] = (((s * 2 + q1) ^ r8) << 4);
        bXor[s] = (((s * 2 + qc) ^ r8) << 4);
    }

    // --- prologue: stage chunk 0 into buf0, invy tile ---
    {
        const uint32_t db = sb + SM_HDR;
#pragma unroll
        for (int r = 0; r < 2; r++) {
            CP16(db + AH_OFF + aswo[r], Ahp + ago[r]);
            CP16(db + AL_OFF + aswo[r], Alp + ago[r]);
        }
#pragma unroll
        for (int r = 0; r < 4; r++) {
            CP16(db + BH_OFF + bswo[r], Bhp + bgo[r]);
            CP16(db + BL_OFF + bswo[r], Blp + bgo[r]);
        }
        if (tid < 32) CP16(sb + (tid << 4), invy_b + tid * 4);
    }
    CP_WAIT_ALL();
    __syncthreads();

    float acc[2][4][4];
#pragma unroll
    for (int i = 0; i < 2; i++)
#pragma unroll
        for (int j = 0; j < 4; j++)
#pragma unroll
            for (int d = 0; d < 4; d++) acc[i][j][d] = 0.0f;

    for (int c = 0; c < 8; c++) {
        const int p = c & 1;
        // stage next chunk
        if (c < 7) {
            const int nkc = (c + 1) * 32;
            const uint32_t db = sb + SM_HDR + ((c + 1) & 1) * STAGE_B;
#pragma unroll
            for (int r = 0; r < 2; r++) {
                CP16(db + AH_OFF + aswo[r], Ahp + ago[r] + nkc);
                CP16(db + AL_OFF + aswo[r], Alp + ago[r] + nkc);
            }
#pragma unroll
            for (int r = 0; r < 4; r++) {
                CP16(db + BH_OFF + bswo[r], Bhp + bgo[r] + nkc);
                CP16(db + BL_OFF + bswo[r], Blp + bgo[r] + nkc);
            }
        }
        // compute on buf p
        const uint32_t bb = sb + SM_HDR + p * STAGE_B;
#pragma unroll
        for (int s = 0; s < 4; s++) {
            uint32_t ah[2][4], al[2][4], bh[2][4], bl[2][4];
#pragma unroll
            for (int i = 0; i < 2; i++) {
                ldm4(ah[i], bb + AH_OFF + aBase[i] + aXor[s]);
                ldm4(al[i], bb + AL_OFF + aBase[i] + aXor[s]);
            }
#pragma unroll
            for (int t = 0; t < 2; t++) {
                ldm4(bh[t], bb + BH_OFF + bBase[t] + bXor[s]);
                ldm4(bl[t], bb + BL_OFF + bBase[t] + bXor[s]);
            }
#pragma unroll
            for (int i = 0; i < 2; i++)
#pragma unroll
                for (int j = 0; j < 4; j++) {
                    const uint32_t* bhf = &bh[j >> 1][(j & 1) * 2];
                    const uint32_t* blf = &bl[j >> 1][(j & 1) * 2];
                    mma_tf32(acc[i][j], ah[i], bhf);   // hi*hi
                    mma_tf32(acc[i][j], ah[i], blf);   // hi*lo
                    mma_tf32(acc[i][j], al[i], bhf);   // lo*hi
                }
        }
        CP_WAIT_ALL();
        __syncthreads();
    }

    // --- epilogue: per-thread argmax over this tile's 32 m-cols ---
    float best[4];
    int   bidx[4];
#pragma unroll
    for (int k = 0; k < 4; k++) { best[k] = -1e30f; bidx[k] = 0; }

    const float* iv = (const float*)smem;
#pragma unroll
    for (int i = 0; i < 2; i++) {
        const int k0 = i * 2, k1 = i * 2 + 1;
#pragma unroll
        for (int j = 0; j < 4; j++) {
            const int mc = warpM * 32 + j * 8 + 2 * (lane & 3);
            const int gm = mt + mc;
            const float iv0 = iv[mc], iv1 = iv[mc + 1];
            float v0 = acc[i][j][0] * iv0;
            float v1 = acc[i][j][1] * iv1;
            float v2 = acc[i][j][2] * iv0;
            float v3 = acc[i][j][3] * iv1;
            if (v0 > best[k0]) { best[k0] = v0; bidx[k0] = gm; }
            if (v1 > best[k0]) { best[k0] = v1; bidx[k0] = gm + 1; }
            if (v2 > best[k1]) { best[k1] = v2; bidx[k1] = gm; }
            if (v3 > best[k1]) { best[k1] = v3; bidx[k1] = gm + 1; }
        }
    }

    // reduce across the 4 lanes sharing each row (lane&3 varies)
#pragma unroll
    for (int s = 1; s < 4; s <<= 1) {
#pragma unroll
        for (int k = 0; k < 4; k++) {
            float ov = __shfl_xor_sync(0xffffffffu, best[k], s);
            int   oi = __shfl_xor_sync(0xffffffffu, bidx[k], s);
            if (ov > best[k] || (ov == best[k] && oi < bidx[k])) {
                best[k] = ov; bidx[k] = oi;
            }
        }
    }

    // cross-warpM reduce via smem (alias dead stage-0 buffer)
    float (*sb_best)[64] = (float(*)[64])(smem + SM_HDR);
    int   (*sb_idx)[64]  = (int(*)[64])(smem + SM_HDR + 1024);
    __syncthreads();
    if ((lane & 3) == 0) {
#pragma unroll
        for (int k = 0; k < 4; k++) {
            int row = warpN * 32 + (k >> 1) * 16 + (k & 1) * 8 + (lane >> 2);
            sb_best[warpM][row] = best[k];
            sb_idx[warpM][row]  = bidx[k];
        }
    }
    __syncthreads();

    if (tid < 64) {
        float fb = sb_best[0][tid];
        int   fi = sb_idx[0][tid];
#pragma unroll
        for (int w = 1; w < 4; w++) {
            float ov = sb_best[w][tid];
            int   oi = sb_idx[w][tid];
            if (ov > fb || (ov == fb && oi < fi)) { fb = ov; fi = oi; }
        }
        const int gi = b * NN + n0 + tid;
        g_pmax[gi * NMT + mtIdx] = fb;
        g_pidx[gi * NMT + mtIdx] = fi;
    }
}

// ---------------------------------------------------------------------------
// Kernel 3: reduce 16 partials per row (ascending mt -> first-max wins),
// scale by invx, gather matched points.
// ---------------------------------------------------------------------------
__global__ void final_kernel(const float* __restrict__ pts,
                             float* __restrict__ out) {
    const int r = blockIdx.x * blockDim.x + threadIdx.x;   // 0..16383
    if (r >= BB * NN) return;
    float fb = -1e30f;
    int   fi = 0;
#pragma unroll
    for (int t = 0; t < NMT; t++) {
        float v = g_pmax[r * NMT + t];
        int   i = g_pidx[r * NMT + t];
        if (v > fb || (v == fb && i < fi)) { fb = v; fi = i; }
    }
    const int b = r >> 11;
    out[(size_t)BB * NN * 2 + r] = fb * g_invx[r];          // confidence
    const float* pp = pts + ((size_t)b * MM + fi) * 2;
    out[(size_t)r * 2 + 0] = pp[0];                          // matched x
    out[(size_t)r * 2 + 1] = pp[1];                          // matched y
}

// ---------------------------------------------------------------------------
extern "C" void kernel_launch(void* const* d_in, const int* in_sizes, int n_in,
                              void* d_out, int out_size) {
    const float* desc_src   = (const float*)d_in[0];
    const float* desc_dst   = (const float*)d_in[1];
    const float* points_dst = (const float*)d_in[2];
    float* out = (float*)d_out;

    cudaFuncSetAttribute(match_kernel,
                         cudaFuncAttributeMaxDynamicSharedMemorySize, SMEM_SZ);

    const int total_rows = BB * NN + BB * MM;   // 32768 rows, 1 warp each
    prep_kernel<<<(total_rows + 7) / 8, 256>>>(desc_src, desc_dst);

    dim3 grid(NMT, NN / 64, BB);                // 16 x 32 x 8 = 4096 tiles
    match_kernel<<<grid, 256, SMEM_SZ>>>();

    final_kernel<<<(BB * NN) / 256, 256>>>(points_dst, out);
}

// round 8
// speedup vs baseline: 4.3429x; 1.7589x over previous
#include <cuda_runtime.h>
#include <cuda_fp16.h>
#include <math.h>
#include <stdint.h>

// Problem shape (fixed)
#define BB 8
#define NN 2048
#define MM 2048
#define DD 256

#define TOT (BB * NN * DD)
#define NMT 16                       // number of M tiles (partials per row)

// fp16-split scratch (hi = fp16-rn(x), lo = fp16-rn(x - hi))
__device__ __align__(16) __half g_Ah[TOT];
__device__ __align__(16) __half g_Al[TOT];
__device__ __align__(16) __half g_Bh[TOT];
__device__ __align__(16) __half g_Bl[TOT];
__device__ float g_invx[BB * NN];
__device__ float g_invy[BB * MM];
// per-(row, mtile) partial argmax
__device__ float g_pmax[BB * NN * NMT];
__device__ int   g_pidx[BB * NN * NMT];

// ---------------------------------------------------------------------------
// PTX helpers (baseline sm_80-class; valid on plain sm_103 target)
// ---------------------------------------------------------------------------
__device__ __forceinline__ uint32_t smem_u32(const void* p) {
    uint32_t a;
    asm("{ .reg .u64 t; cvta.to.shared.u64 t, %1; cvt.u32.u64 %0, t; }"
        : "=r"(a) : "l"(p));
    return a;
}
#define CP16(sm, gp) \
    asm volatile("cp.async.cg.shared.global [%0], [%1], 16;" \
                 :: "r"(sm), "l"(gp) : "memory")
#define CP_WAIT_ALL() asm volatile("cp.async.wait_all;" ::: "memory")

__device__ __forceinline__ void ldm4(uint32_t* r, uint32_t addr) {
    asm volatile("ldmatrix.sync.aligned.m8n8.x4.shared.b16 {%0,%1,%2,%3}, [%4];"
        : "=r"(r[0]), "=r"(r[1]), "=r"(r[2]), "=r"(r[3]) : "r"(addr));
}
// m16n8k16 fp16 MMA, fp32 accumulate
__device__ __forceinline__ void mma_f16(float* d, const uint32_t* a, const uint32_t* b) {
    asm volatile("mma.sync.aligned.m16n8k16.row.col.f32.f16.f16.f32 "
        "{%0,%1,%2,%3}, {%4,%5,%6,%7}, {%8,%9}, {%0,%1,%2,%3};"
        : "+f"(d[0]), "+f"(d[1]), "+f"(d[2]), "+f"(d[3])
        : "r"(a[0]), "r"(a[1]), "r"(a[2]), "r"(a[3]), "r"(b[0]), "r"(b[1]));
}

// ---------------------------------------------------------------------------
// Kernel 1: fused per-row norm + fp16 split. One warp per row (256 floats).
// ---------------------------------------------------------------------------
__global__ void prep_kernel(const float* __restrict__ src,
                            const float* __restrict__ dst) {
    int gwarp = (blockIdx.x * blockDim.x + threadIdx.x) >> 5;
    int lane  = threadIdx.x & 31;
    const int total = BB * NN + BB * MM;
    if (gwarp >= total) return;

    const float* p;
    float* outp;
    __half *ho, *lo;
    size_t ro;
    if (gwarp < BB * NN) {
        ro = (size_t)gwarp * DD;
        p = src + ro; ho = g_Ah + ro; lo = g_Al + ro; outp = &g_invx[gwarp];
    } else {
        int r = gwarp - BB * NN;
        ro = (size_t)r * DD;
        p = dst + ro; ho = g_Bh + ro; lo = g_Bl + ro; outp = &g_invy[r];
    }
    float s = 0.0f;
#pragma unroll
    for (int h = 0; h < 2; h++) {
        float4 v = ((const float4*)p)[lane + 32 * h];
        s += v.x * v.x + v.y * v.y + v.z * v.z + v.w * v.w;
        __half hx = __float2half_rn(v.x);
        __half hy = __float2half_rn(v.y);
        __half hz = __float2half_rn(v.z);
        __half hw = __float2half_rn(v.w);
        __half lx = __float2half_rn(v.x - __half2float(hx));
        __half ly = __float2half_rn(v.y - __half2float(hy));
        __half lz = __float2half_rn(v.z - __half2float(hz));
        __half lw = __float2half_rn(v.w - __half2float(hw));
        __half2* hop = (__half2*)(ho + lane * 4 + h * 128);
        __half2* lop = (__half2*)(lo + lane * 4 + h * 128);
        hop[0] = __halves2half2(hx, hy);
        hop[1] = __halves2half2(hz, hw);
        lop[0] = __halves2half2(lx, ly);
        lop[1] = __halves2half2(lz, lw);
    }
#pragma unroll
    for (int o = 16; o > 0; o >>= 1) s += __shfl_xor_sync(0xffffffffu, s, o);
    if (lane == 0) *outp = 1.0f / fmaxf(sqrtf(s), 1e-12f);
}

// ---------------------------------------------------------------------------
// Kernel 2: fp16 HMMA (3-term split) tile GEMM + per-tile argmax partial.
// One CTA = one 64(n) x 128(m) x 256(K) tile; grid 16(mt) x 32(nt) x 8(b).
// 256 threads (8 warps = 2(n) x 4(m)); warp tile 32x32; 2 CTAs/SM.
// K streamed in 4 chunks of 64 halves (128B rows, SW128); double-buffered.
// ---------------------------------------------------------------------------
#define AH_OFF 0
#define AL_OFF 8192
#define BH_OFF 16384
#define BL_OFF 32768
#define STAGE_B 49152
#define SM_HDR 1024                     // invy tile (512B used)
#define SMEM_SZ (SM_HDR + 2 * STAGE_B)  // 99328

__global__ __launch_bounds__(256, 2)
void match_kernel() {
    extern __shared__ char smem[];
    const uint32_t sb = smem_u32(smem);
    const int tid  = threadIdx.x;
    const int wid  = tid >> 5;
    const int lane = tid & 31;
    const int mtIdx = blockIdx.x;
    const int mt   = mtIdx * 128;
    const int n0   = blockIdx.y * 64;
    const int b    = blockIdx.z;
    const int warpN = wid >> 2;        // 0..1 -> n offset 32*warpN
    const int warpM = wid & 3;         // 0..3 -> m offset 32*warpM

    // global byte pointers (rows are 512B = 256 halves)
    const char* Ahp = (const char*)g_Ah + ((size_t)b * NN + n0) * 512;
    const char* Alp = (const char*)g_Al + ((size_t)b * NN + n0) * 512;
    const char* Bhp = (const char*)g_Bh + ((size_t)b * MM + mt) * 512;
    const char* Blp = (const char*)g_Bl + ((size_t)b * MM + mt) * 512;
    const float* invy_b = &g_invy[b * MM + mt];

    // --- staging geometry (per chunk: A 64x128B, B 128x128B) ---
    // A: 512 16B-units -> 2 per thread; B: 1024 -> 4 per thread
    int aswo[2], ago[2];
#pragma unroll
    for (int r = 0; r < 2; r++) {
        int id = tid + 256 * r;
        int row = id >> 3, c4 = id & 7;
        aswo[r] = row * 128 + ((c4 ^ (row & 7)) << 4);
        ago[r]  = row * 512 + c4 * 16;
    }
    int bswo[4], bgo[4];
#pragma unroll
    for (int r = 0; r < 4; r++) {
        int id = tid + 256 * r;
        int row = id >> 3, c4 = id & 7;
        bswo[r] = row * 128 + ((c4 ^ (row & 7)) << 4);
        bgo[r]  = row * 512 + c4 * 16;
    }

    // --- ldmatrix fragment addresses (fp16 m16n8k16) ---
    // A x4: lanes 0-15 -> rows 0-15 k-block 0; lanes 16-31 -> rows 0-15 k-block 1
    const int aRow = lane & 15;
    const int aK16 = lane >> 4;            // +16B for k8-15
    int aBase[2], aXor[4];
#pragma unroll
    for (int i = 0; i < 2; i++)
        aBase[i] = (warpN * 32 + i * 16 + aRow) * 128;
    // B x4 (paired j-tiles): lanes 0-7 rows0-7/k0, 8-15 rows0-7/k1,
    //                        16-23 rows8-15/k0, 24-31 rows8-15/k1
    const int bRow = ((lane >> 4) << 3) + (lane & 7);
    const int bK16 = (lane >> 3) & 1;
    int bBase[2], bXor[4];
#pragma unroll
    for (int t = 0; t < 2; t++)
        bBase[t] = (warpM * 32 + t * 16 + bRow) * 128;
#pragma unroll
    for (int s = 0; s < 4; s++) {          // s = k-step of 16 halves (32B)
        aXor[s] = (((s * 2 + aK16) ^ (aRow & 7)) << 4);
        bXor[s] = (((s * 2 + bK16) ^ (bRow & 7)) << 4);
    }

    // --- prologue: stage chunk 0 into buf0, invy tile ---
    {
        const uint32_t db = sb + SM_HDR;
#pragma unroll
        for (int r = 0; r < 2; r++) {
            CP16(db + AH_OFF + aswo[r], Ahp + ago[r]);
            CP16(db + AL_OFF + aswo[r], Alp + ago[r]);
        }
#pragma unroll
        for (int r = 0; r < 4; r++) {
            CP16(db + BH_OFF + bswo[r], Bhp + bgo[r]);
            CP16(db + BL_OFF + bswo[r], Blp + bgo[r]);
        }
        if (tid < 32) CP16(sb + (tid << 4), invy_b + tid * 4);
    }
    CP_WAIT_ALL();
    __syncthreads();

    float acc[2][4][4];
#pragma unroll
    for (int i = 0; i < 2; i++)
#pragma unroll
        for (int j = 0; j < 4; j++)
#pragma unroll
            for (int d = 0; d < 4; d++) acc[i][j][d] = 0.0f;

    for (int c = 0; c < 4; c++) {          // 4 chunks of 64 K-halves
        const int p = c & 1;
        // stage next chunk
        if (c < 3) {
            const int nko = (c + 1) * 128;  // byte offset within row
            const uint32_t db = sb + SM_HDR + ((c + 1) & 1) * STAGE_B;
#pragma unroll
            for (int r = 0; r < 2; r++) {
                CP16(db + AH_OFF + aswo[r], Ahp + ago[r] + nko);
                CP16(db + AL_OFF + aswo[r], Alp + ago[r] + nko);
            }
#pragma unroll
            for (int r = 0; r < 4; r++) {
                CP16(db + BH_OFF + bswo[r], Bhp + bgo[r] + nko);
                CP16(db + BL_OFF + bswo[r], Blp + bgo[r] + nko);
            }
        }
        // compute on buf p
        const uint32_t bb = sb + SM_HDR + p * STAGE_B;
#pragma unroll
        for (int s = 0; s < 4; s++) {
            uint32_t ah[2][4], al[2][4], bh[2][4], bl[2][4];
#pragma unroll
            for (int i = 0; i < 2; i++) {
                ldm4(ah[i], bb + AH_OFF + aBase[i] + aXor[s]);
                ldm4(al[i], bb + AL_OFF + aBase[i] + aXor[s]);
            }
#pragma unroll
            for (int t = 0; t < 2; t++) {
                ldm4(bh[t], bb + BH_OFF + bBase[t] + bXor[s]);
                ldm4(bl[t], bb + BL_OFF + bBase[t] + bXor[s]);
            }
#pragma unroll
            for (int i = 0; i < 2; i++)
#pragma unroll
                for (int j = 0; j < 4; j++) {
                    const uint32_t* bhf = &bh[j >> 1][(j & 1) * 2];
                    const uint32_t* blf = &bl[j >> 1][(j & 1) * 2];
                    mma_f16(acc[i][j], ah[i], bhf);   // hi*hi
                    mma_f16(acc[i][j], ah[i], blf);   // hi*lo
                    mma_f16(acc[i][j], al[i], bhf);   // lo*hi
                }
        }
        CP_WAIT_ALL();
        __syncthreads();
    }

    // --- epilogue: per-thread argmax over this tile's 32 m-cols ---
    float best[4];
    int   bidx[4];
#pragma unroll
    for (int k = 0; k < 4; k++) { best[k] = -1e30f; bidx[k] = 0; }

    const float* iv = (const float*)smem;
#pragma unroll
    for (int i = 0; i < 2; i++) {
        const int k0 = i * 2, k1 = i * 2 + 1;
#pragma unroll
        for (int j = 0; j < 4; j++) {
            const int mc = warpM * 32 + j * 8 + 2 * (lane & 3);
            const int gm = mt + mc;
            const float iv0 = iv[mc], iv1 = iv[mc + 1];
            float v0 = acc[i][j][0] * iv0;
            float v1 = acc[i][j][1] * iv1;
            float v2 = acc[i][j][2] * iv0;
            float v3 = acc[i][j][3] * iv1;
            if (v0 > best[k0]) { best[k0] = v0; bidx[k0] = gm; }
            if (v1 > best[k0]) { best[k0] = v1; bidx[k0] = gm + 1; }
            if (v2 > best[k1]) { best[k1] = v2; bidx[k1] = gm; }
            if (v3 > best[k1]) { best[k1] = v3; bidx[k1] = gm + 1; }
        }
    }

    // reduce across the 4 lanes sharing each row (lane&3 varies)
#pragma unroll
    for (int s = 1; s < 4; s <<= 1) {
#pragma unroll
        for (int k = 0; k < 4; k++) {
            float ov = __shfl_xor_sync(0xffffffffu, best[k], s);
            int   oi = __shfl_xor_sync(0xffffffffu, bidx[k], s);
            if (ov > best[k] || (ov == best[k] && oi < bidx[k])) {
                best[k] = ov; bidx[k] = oi;
            }
        }
    }

    // cross-warpM reduce via smem (alias dead stage-0 buffer)
    float (*sb_best)[64] = (float(*)[64])(smem + SM_HDR);
    int   (*sb_idx)[64]  = (int(*)[64])(smem + SM_HDR + 1024);
    __syncthreads();
    if ((lane & 3) == 0) {
#pragma unroll
        for (int k = 0; k < 4; k++) {
            int row = warpN * 32 + (k >> 1) * 16 + (k & 1) * 8 + (lane >> 2);
            sb_best[warpM][row] = best[k];
            sb_idx[warpM][row]  = bidx[k];
        }
    }
    __syncthreads();

    if (tid < 64) {
        float fb = sb_best[0][tid];
        int   fi = sb_idx[0][tid];
#pragma unroll
        for (int w = 1; w < 4; w++) {
            float ov = sb_best[w][tid];
            int   oi = sb_idx[w][tid];
            if (ov > fb || (ov == fb && oi < fi)) { fb = ov; fi = oi; }
        }
        const int gi = b * NN + n0 + tid;
        g_pmax[gi * NMT + mtIdx] = fb;
        g_pidx[gi * NMT + mtIdx] = fi;
    }
}

// ---------------------------------------------------------------------------
// Kernel 3: reduce 16 partials per row (ascending mt -> first-max wins),
// scale by invx, gather matched points.
// ---------------------------------------------------------------------------
__global__ void final_kernel(const float* __restrict__ pts,
                             float* __restrict__ out) {
    const int r = blockIdx.x * blockDim.x + threadIdx.x;   // 0..16383
    if (r >= BB * NN) return;
    float fb = -1e30f;
    int   fi = 0;
#pragma unroll
    for (int t = 0; t < NMT; t++) {
        float v = g_pmax[r * NMT + t];
        int   i = g_pidx[r * NMT + t];
        if (v > fb || (v == fb && i < fi)) { fb = v; fi = i; }
    }
    const int b = r >> 11;
    out[(size_t)BB * NN * 2 + r] = fb * g_invx[r];          // confidence
    const float* pp = pts + ((size_t)b * MM + fi) * 2;
    out[(size_t)r * 2 + 0] = pp[0];                          // matched x
    out[(size_t)r * 2 + 1] = pp[1];                          // matched y
}

// ---------------------------------------------------------------------------
extern "C" void kernel_launch(void* const* d_in, const int* in_sizes, int n_in,
                              void* d_out, int out_size) {
    const float* desc_src   = (const float*)d_in[0];
    const float* desc_dst   = (const float*)d_in[1];
    const float* points_dst = (const float*)d_in[2];
    float* out = (float*)d_out;

    cudaFuncSetAttribute(match_kernel,
                         cudaFuncAttributeMaxDynamicSharedMemorySize, SMEM_SZ);

    const int total_rows = BB * NN + BB * MM;   // 32768 rows, 1 warp each
    prep_kernel<<<(total_rows + 7) / 8, 256>>>(desc_src, desc_dst);

    dim3 grid(NMT, NN / 64, BB);                // 16 x 32 x 8 = 4096 tiles
    match_kernel<<<grid, 256, SMEM_SZ>>>();

    final_kernel<<<(BB * NN) / 256, 256>>>(points_dst, out);
}